// round 1
// baseline (speedup 1.0000x reference)
#include <cuda_runtime.h>

#define BATCH 32768
#define NCODES 8192
#define DIM 256

// Scratch (allocation-free rule: __device__ globals)
__device__ float  g_z2[BATCH];
__device__ float  g_e2[NCODES];
__device__ int    g_idx[BATCH];
__device__ double g_part[BATCH];

// ---------------------------------------------------------------------------
// Row sum-of-squares, XLA-GPU-style order: one warp per row, lane strided by
// 32 with fma accumulation, then shfl-down tree. This must reproduce the
// reference's jnp.sum(x*x, axis=1) bit pattern as closely as possible because
// z2 phases the fp32 rounding grid of the distance computation.
// ---------------------------------------------------------------------------
__global__ void rowsq_z_kernel(const float* __restrict__ x) {
    int warp = (blockIdx.x * blockDim.x + threadIdx.x) >> 5;
    int lane = threadIdx.x & 31;
    if (warp >= BATCH) return;
    const float* r = x + (size_t)warp * DIM;
    float acc = 0.f;
#pragma unroll
    for (int j = 0; j < DIM; j += 32) {
        float v = r[j + lane];
        acc = fmaf(v, v, acc);
    }
#pragma unroll
    for (int off = 16; off; off >>= 1)
        acc += __shfl_down_sync(0xffffffffu, acc, off);
    if (lane == 0) g_z2[warp] = acc;
}

__global__ void rowsq_e_kernel(const float* __restrict__ x) {
    int warp = (blockIdx.x * blockDim.x + threadIdx.x) >> 5;
    int lane = threadIdx.x & 31;
    if (warp >= NCODES) return;
    const float* r = x + (size_t)warp * DIM;
    float acc = 0.f;
#pragma unroll
    for (int j = 0; j < DIM; j += 32) {
        float v = r[j + lane];
        acc = fmaf(v, v, acc);
    }
#pragma unroll
    for (int off = 16; off; off >>= 1)
        acc += __shfl_down_sync(0xffffffffu, acc, off);
    if (lane == 0) g_e2[warp] = acc;
}

// ---------------------------------------------------------------------------
// Fused distance GEMM + argmin.
// Block: 128 rows x all 8192 codes, 256 threads, 8x8 register tiles,
// K tiles of 128 codes, D chunks of 32.
// dist = fl(fl(z2 + e2) - 2*ze)  — exactly the reference's expression tree.
// Tie-break: lowest code index (jnp.argmin first-occurrence semantics).
// ---------------------------------------------------------------------------
#define BR 128
#define BC 128
#define DC 32
#define PAD 4

__global__ __launch_bounds__(256, 2)
void dist_argmin_kernel(const float* __restrict__ Z, const float* __restrict__ C) {
    __shared__ float sz[DC][BR + PAD];
    __shared__ float sc[DC][BC + PAD];

    const int tid = threadIdx.x;
    const int tx = tid & 15;   // col group
    const int ty = tid >> 4;   // row group
    const int rowBase = blockIdx.x * BR;

    float z2r[8];
#pragma unroll
    for (int i = 0; i < 8; i++) z2r[i] = g_z2[rowBase + ty * 8 + i];

    float bestv[8];
    int   besti[8];
#pragma unroll
    for (int i = 0; i < 8; i++) {
        bestv[i] = __int_as_float(0x7f800000);  // +inf
        besti[i] = 0;
    }

    for (int kt = 0; kt < NCODES; kt += BC) {
        float acc[8][8];
#pragma unroll
        for (int i = 0; i < 8; i++)
#pragma unroll
            for (int j = 0; j < 8; j++) acc[i][j] = 0.f;

        for (int dc = 0; dc < DIM; dc += DC) {
            // cooperative transposed tile load: smem[d][row]
#pragma unroll
            for (int l = 0; l < 4; l++) {
                int i4 = tid + l * 256;     // float4 index, 0..1023
                int r  = i4 >> 3;           // 0..127
                int dd = (i4 & 7) * 4;      // 0,4,...,28
                float4 v = *(const float4*)(Z + (size_t)(rowBase + r) * DIM + dc + dd);
                sz[dd + 0][r] = v.x; sz[dd + 1][r] = v.y;
                sz[dd + 2][r] = v.z; sz[dd + 3][r] = v.w;
                float4 w = *(const float4*)(C + (size_t)(kt + r) * DIM + dc + dd);
                sc[dd + 0][r] = w.x; sc[dd + 1][r] = w.y;
                sc[dd + 2][r] = w.z; sc[dd + 3][r] = w.w;
            }
            __syncthreads();
#pragma unroll
            for (int d = 0; d < DC; d++) {
                float a[8], b[8];
                *(float4*)(a)     = *(const float4*)&sz[d][ty * 8];
                *(float4*)(a + 4) = *(const float4*)&sz[d][ty * 8 + 4];
                *(float4*)(b)     = *(const float4*)&sc[d][tx * 8];
                *(float4*)(b + 4) = *(const float4*)&sc[d][tx * 8 + 4];
#pragma unroll
                for (int i = 0; i < 8; i++)
#pragma unroll
                    for (int j = 0; j < 8; j++)
                        acc[i][j] = fmaf(a[i], b[j], acc[i][j]);
            }
            __syncthreads();
        }

        // epilogue for this code tile: distances + running argmin
#pragma unroll
        for (int j = 0; j < 8; j++) {
            int c = kt + tx * 8 + j;
            float e2 = __ldg(&g_e2[c]);
#pragma unroll
            for (int i = 0; i < 8; i++) {
                float t = z2r[i] + e2;               // fl(z2 + e2)
                float dist = fmaf(-2.f, acc[i][j], t); // fl(t - 2*ze), exact match
                if (dist < bestv[i]) { bestv[i] = dist; besti[i] = c; }
            }
        }
    }

    // cross-thread lexicographic (value, index) reduction — reuse tile smem
    float (*rv)[16] = (float(*)[16]) & sz[0][0];  // 128*16 floats fits in sz
    int   (*ri)[16] = (int  (*)[16]) & sc[0][0];
    __syncthreads();
#pragma unroll
    for (int i = 0; i < 8; i++) {
        rv[ty * 8 + i][tx] = bestv[i];
        ri[ty * 8 + i][tx] = besti[i];
    }
    __syncthreads();
    if (tid < BR) {
        float bv = rv[tid][0];
        int   bi = ri[tid][0];
#pragma unroll
        for (int t = 1; t < 16; t++) {
            float v = rv[tid][t];
            int  ii = ri[tid][t];
            if (v < bv || (v == bv && ii < bi)) { bv = v; bi = ii; }
        }
        g_idx[rowBase + tid] = bi;
    }
}

// ---------------------------------------------------------------------------
// Gather + straight-through output + per-row partial MSE sums (double).
// One block per row, 256 threads = 256 dims.
// ---------------------------------------------------------------------------
__global__ void gather_kernel(const float* __restrict__ Z, const float* __restrict__ C,
                              float* __restrict__ outZ, float* __restrict__ outIdx) {
    int row = blockIdx.x;
    int d = threadIdx.x;
    int idx = g_idx[row];
    float ze = Z[(size_t)row * DIM + d];
    float e  = C[(size_t)idx * DIM + d];
    float diff = e - ze;       // z_q - z_e (fp32, as reference)
    float st = ze + diff;      // straight-through: z_e + (z_q - z_e)
    outZ[(size_t)row * DIM + d] = st;
    float sq = diff * diff;    // same square feeds both losses

    __shared__ double red[256];
    red[d] = (double)sq;
    __syncthreads();
#pragma unroll
    for (int off = 128; off; off >>= 1) {
        if (d < off) red[d] += red[d + off];
        __syncthreads();
    }
    if (d == 0) {
        g_part[row] = red[0];
        outIdx[row] = (float)idx;
    }
}

__global__ void finalize_kernel(float* __restrict__ outS) {
    __shared__ double red[256];
    int t = threadIdx.x;
    double s = 0.0;
    for (int i = t; i < BATCH; i += 256) s += g_part[i];
    red[t] = s;
    __syncthreads();
#pragma unroll
    for (int off = 128; off; off >>= 1) {
        if (t < off) red[t] += red[t + off];
        __syncthreads();
    }
    if (t == 0) {
        float cb = (float)(red[0] / (double)((size_t)BATCH * DIM));
        float commit = cb;                 // identical elementwise squares
        float vq = cb + 0.25f * commit;    // BETA = 0.25
        outS[0] = vq;
        outS[1] = cb;
        outS[2] = commit;
    }
}

// ---------------------------------------------------------------------------
extern "C" void kernel_launch(void* const* d_in, const int* in_sizes, int n_in,
                              void* d_out, int out_size) {
    (void)in_sizes; (void)n_in; (void)out_size;
    const float* Z = (const float*)d_in[0];
    const float* C = (const float*)d_in[1];
    float* out    = (float*)d_out;
    float* outZ   = out;
    float* outIdx = out + (size_t)BATCH * DIM;
    float* outS   = outIdx + BATCH;

    rowsq_z_kernel<<<(BATCH * 32) / 256, 256>>>(Z);
    rowsq_e_kernel<<<(NCODES * 32) / 256, 256>>>(C);
    dist_argmin_kernel<<<BATCH / BR, 256>>>(Z, C);
    gather_kernel<<<BATCH, 256>>>(Z, C, outZ, outIdx);
    finalize_kernel<<<1, 256>>>(outS);
}

// round 3
// speedup vs baseline: 2.6537x; 2.6537x over previous
#include <cuda_runtime.h>
#include <cstdint>

#define BATCH  32768
#define NCODES 8192
#define DIM    256
#define BM     128
#define BN     128
#define NCT    (NCODES / BN)     // 64 code tiles
#define CAP    32
#define MARGIN 1e-4f

// ---------------- device scratch (no allocations allowed) ----------------
__device__ float  g_z2[BATCH];
__device__ float  g_e2[NCODES];
__device__ int    g_idx[BATCH];
__device__ double g_part[BATCH];
__device__ int    g_candIdx[BATCH * CAP];
__device__ int    g_candCnt[BATCH];

// ---------------- smem layout for the mma kernel ----------------
// A permuted: 8 mtiles x 32 ktiles x (512B tile + 16B pad)
#define ATILE   528
#define SMA_OFF 0
#define SMA_SZ  (8 * 32 * ATILE)                  // 135168
// B permuted double buffer: 16 ntiles x 8 ktiles x (256B + 16B pad)
#define BTILE   272
#define BBUF_SZ (16 * 8 * BTILE)                  // 34816
#define SMB0    (SMA_OFF + SMA_SZ)
#define SMB1    (SMB0 + BBUF_SZ)
#define SMQB    (SMB1 + BBUF_SZ)                  // qbuf[128][4] floats
#define SMRM    (SMQB + 128 * 4 * 4)              // rowmin[128] floats
#define SM_TOT  (SMRM + 128 * 4)                  // 207360 bytes

__device__ __forceinline__ float to_tf32(float x) {
    uint32_t r; asm("cvt.rna.tf32.f32 %0, %1;" : "=r"(r) : "f"(x));
    return __uint_as_float(r);
}

__device__ __forceinline__ void mma_tf32(float* d, const uint4& a, const uint2& b) {
    asm volatile(
        "mma.sync.aligned.m16n8k8.row.col.f32.tf32.tf32.f32 "
        "{%0,%1,%2,%3}, {%4,%5,%6,%7}, {%8,%9}, {%0,%1,%2,%3};"
        : "+f"(d[0]), "+f"(d[1]), "+f"(d[2]), "+f"(d[3])
        : "r"(a.x), "r"(a.y), "r"(a.z), "r"(a.w), "r"(b.x), "r"(b.y));
}

// ---------------- init ----------------
__global__ void init_kernel() {
    int i = blockIdx.x * blockDim.x + threadIdx.x;
    if (i < BATCH) g_candCnt[i] = 0;
}

// ---------------- row sum-of-squares (bit-matches reference rounding grid) ----
__global__ void rowsq_z_kernel(const float* __restrict__ x) {
    int warp = (blockIdx.x * blockDim.x + threadIdx.x) >> 5;
    int lane = threadIdx.x & 31;
    if (warp >= BATCH) return;
    const float* r = x + (size_t)warp * DIM;
    float acc = 0.f;
#pragma unroll
    for (int j = 0; j < DIM; j += 32) { float v = r[j + lane]; acc = fmaf(v, v, acc); }
#pragma unroll
    for (int off = 16; off; off >>= 1) acc += __shfl_down_sync(0xffffffffu, acc, off);
    if (lane == 0) g_z2[warp] = acc;
}
__global__ void rowsq_e_kernel(const float* __restrict__ x) {
    int warp = (blockIdx.x * blockDim.x + threadIdx.x) >> 5;
    int lane = threadIdx.x & 31;
    if (warp >= NCODES) return;
    const float* r = x + (size_t)warp * DIM;
    float acc = 0.f;
#pragma unroll
    for (int j = 0; j < DIM; j += 32) { float v = r[j + lane]; acc = fmaf(v, v, acc); }
#pragma unroll
    for (int off = 16; off; off >>= 1) acc += __shfl_down_sync(0xffffffffu, acc, off);
    if (lane == 0) g_e2[warp] = acc;
}

// ---------------- tf32 mma distance kernel + candidate capture ----------------
__global__ __launch_bounds__(256, 1)
void dist_mma_kernel(const float* __restrict__ Z, const float* __restrict__ C) {
    extern __shared__ char sm[];
    const int tid  = threadIdx.x;
    const int wid  = tid >> 5;
    const int lane = tid & 31;
    const int g    = lane >> 2;       // fragment group (row within 8)
    const int tq   = lane & 3;        // thread-in-group (col quad)
    const int wr   = wid >> 2;        // warp row 0..1  (64 rows each)
    const int wc   = wid & 3;         // warp col 0..3  (32 codes each)
    const int rowBase = blockIdx.x * BM;

    float* qbuf   = (float*)(sm + SMQB);   // [128][4]
    float* rowmin = (float*)(sm + SMRM);   // [128]
    if (tid < BM) rowmin[tid] = __int_as_float(0x7f800000);

    // ---- stage A (128 x 256), tf32-rounded, fragment-permuted ----
#pragma unroll
    for (int l = 0; l < 32; l++) {
        int i4 = tid + l * 256;              // 8192 float4
        int r  = i4 >> 6;
        int c4 = i4 & 63;
        float4 v = *(const float4*)(Z + (size_t)(rowBase + r) * DIM + c4 * 4);
        float e[4] = {to_tf32(v.x), to_tf32(v.y), to_tf32(v.z), to_tf32(v.w)};
        int mt = r >> 4, kt = c4 >> 1;
        int base = SMA_OFF + (mt * 32 + kt) * ATILE;
        int slotBase = (c4 & 1) * 2 + ((r >> 3) & 1);
#pragma unroll
        for (int j = 0; j < 4; j++) {
            int lf = ((r & 7) << 2) | j;
            *(float*)(sm + base + lf * 16 + slotBase * 4) = e[j];
        }
    }

    // ---- B chunk staging helpers (128 codes x 64 dims per chunk) ----
    float4 vb[8];
    int vn[8], vc4[8];
    // prologue: chunk (ct=0, kc=0)
#pragma unroll
    for (int t = 0; t < 8; t++) {
        int i4 = tid + t * 256;
        int n = i4 >> 4, c4 = i4 & 15;
        vn[t] = n; vc4[t] = c4;
        vb[t] = *(const float4*)(C + (size_t)n * DIM + c4 * 4);
    }
#pragma unroll
    for (int t = 0; t < 8; t++) {
        int n = vn[t], c4 = vc4[t];
        float e[4] = {to_tf32(vb[t].x), to_tf32(vb[t].y), to_tf32(vb[t].z), to_tf32(vb[t].w)};
        int base = SMB0 + ((n >> 3) * 8 + (c4 >> 1)) * BTILE;
        int slot = c4 & 1;
#pragma unroll
        for (int j = 0; j < 4; j++)
            *(float*)(sm + base + (((n & 7) << 2) | j) * 8 + slot * 4) = e[j];
    }
    __syncthreads();

    int cur = 0;
    for (int ct = 0; ct < NCT; ct++) {
        float acc[4][4][4];
#pragma unroll
        for (int a = 0; a < 4; a++)
#pragma unroll
            for (int b = 0; b < 4; b++)
#pragma unroll
                for (int e = 0; e < 4; e++) acc[a][b][e] = 0.f;

        for (int kc = 0; kc < 4; kc++) {
            const bool hn = !(ct == NCT - 1 && kc == 3);
            if (hn) {  // issue next-chunk global loads early
                int nct = (kc == 3) ? ct + 1 : ct;
                int nkc = (kc + 1) & 3;
                const float* src = C + (size_t)nct * BN * DIM + nkc * 64;
#pragma unroll
                for (int t = 0; t < 8; t++) {
                    int i4 = tid + t * 256;
                    int n = i4 >> 4, c4 = i4 & 15;
                    vn[t] = n; vc4[t] = c4;
                    vb[t] = *(const float4*)(src + (size_t)n * DIM + c4 * 4);
                }
            }
            // ---- mma over 8 k-steps from buf[cur] ----
            const int bbase = cur ? SMB1 : SMB0;
#pragma unroll
            for (int ks = 0; ks < 8; ks++) {
                int ktg = kc * 8 + ks;
                uint4 afr[4];
#pragma unroll
                for (int mt = 0; mt < 4; mt++)
                    afr[mt] = *(const uint4*)(sm + SMA_OFF + ((wr * 4 + mt) * 32 + ktg) * ATILE + lane * 16);
                uint2 bfr[4];
#pragma unroll
                for (int nt = 0; nt < 4; nt++)
                    bfr[nt] = *(const uint2*)(sm + bbase + ((wc * 4 + nt) * 8 + ks) * BTILE + lane * 8);
#pragma unroll
                for (int mt = 0; mt < 4; mt++)
#pragma unroll
                    for (int nt = 0; nt < 4; nt++)
                        mma_tf32(acc[mt][nt], afr[mt], bfr[nt]);
            }
            if (hn) {  // store next chunk to the other buffer
                const int nb = cur ? SMB0 : SMB1;
#pragma unroll
                for (int t = 0; t < 8; t++) {
                    int n = vn[t], c4 = vc4[t];
                    float e[4] = {to_tf32(vb[t].x), to_tf32(vb[t].y), to_tf32(vb[t].z), to_tf32(vb[t].w)};
                    int base = nb + ((n >> 3) * 8 + (c4 >> 1)) * BTILE;
                    int slot = c4 & 1;
#pragma unroll
                    for (int j = 0; j < 4; j++)
                        *(float*)(sm + base + (((n & 7) << 2) | j) * 8 + slot * 4) = e[j];
                }
            }
            __syncthreads();
            cur ^= 1;
        }

        // ---- epilogue: dist = e2 - 2*ze (z2 constant per row, dropped) ----
        const int ctbase = ct * BN;
        float e2v[4][2];
#pragma unroll
        for (int nt = 0; nt < 4; nt++) {
            int c = ctbase + wc * 32 + nt * 8 + 2 * tq;
            e2v[nt][0] = __ldg(&g_e2[c]);
            e2v[nt][1] = __ldg(&g_e2[c + 1]);
        }
        float rmin[8];  // [mt*2 + half]
#pragma unroll
        for (int mt = 0; mt < 4; mt++) {
            float mA = __int_as_float(0x7f800000), mB = mA;
#pragma unroll
            for (int nt = 0; nt < 4; nt++) {
                float d0 = fmaf(-2.f, acc[mt][nt][0], e2v[nt][0]);
                float d1 = fmaf(-2.f, acc[mt][nt][1], e2v[nt][1]);
                float d2 = fmaf(-2.f, acc[mt][nt][2], e2v[nt][0]);
                float d3 = fmaf(-2.f, acc[mt][nt][3], e2v[nt][1]);
                acc[mt][nt][0] = d0; acc[mt][nt][1] = d1;
                acc[mt][nt][2] = d2; acc[mt][nt][3] = d3;
                mA = fminf(mA, fminf(d0, d1));
                mB = fminf(mB, fminf(d2, d3));
            }
            rmin[mt * 2] = mA; rmin[mt * 2 + 1] = mB;
        }
#pragma unroll
        for (int o = 1; o <= 2; o <<= 1)
#pragma unroll
            for (int i = 0; i < 8; i++)
                rmin[i] = fminf(rmin[i], __shfl_xor_sync(0xffffffffu, rmin[i], o));
        if (tq == 0) {
#pragma unroll
            for (int mt = 0; mt < 4; mt++) {
                int rA = wr * 64 + mt * 16 + g;
                qbuf[rA * 4 + wc] = rmin[mt * 2];
                qbuf[(rA + 8) * 4 + wc] = rmin[mt * 2 + 1];
            }
        }
        __syncthreads();
        if (tid < BM) {
            float m = rowmin[tid];
#pragma unroll
            for (int k = 0; k < 4; k++) m = fminf(m, qbuf[tid * 4 + k]);
            rowmin[tid] = m;
        }
        __syncthreads();
        // phase2: append candidates under rowmin + margin
#pragma unroll
        for (int mt = 0; mt < 4; mt++) {
            int rA = wr * 64 + mt * 16 + g;
            float thA = rowmin[rA] + MARGIN;
            float thB = rowmin[rA + 8] + MARGIN;
#pragma unroll
            for (int nt = 0; nt < 4; nt++) {
                int c = ctbase + wc * 32 + nt * 8 + 2 * tq;
#pragma unroll
                for (int e = 0; e < 4; e++) {
                    float d = acc[mt][nt][e];
                    float th = (e < 2) ? thA : thB;
                    if (d < th) {
                        int grow = rowBase + rA + ((e < 2) ? 0 : 8);
                        int code = c + (e & 1);
                        int pos = atomicAdd(&g_candCnt[grow], 1);
                        if (pos < CAP) g_candIdx[grow * CAP + pos] = code;
                    }
                }
            }
        }
        __syncthreads();
    }
}

// ---------------- exact refine (bit-exact fp32 chain, first-index ties) ------
__device__ __forceinline__ float exact_dist(const float4* zr, int code,
                                            const float* __restrict__ C, float z2) {
    const float4* cr = (const float4*)(C + (size_t)code * DIM);
    float acc = 0.f;
#pragma unroll
    for (int d4 = 0; d4 < 64; d4++) {
        float4 a = zr[d4], b = cr[d4];
        acc = fmaf(a.x, b.x, acc); acc = fmaf(a.y, b.y, acc);
        acc = fmaf(a.z, b.z, acc); acc = fmaf(a.w, b.w, acc);
    }
    float t = z2 + g_e2[code];
    return fmaf(-2.f, acc, t);
}

__global__ void refine_kernel(const float* __restrict__ Z, const float* __restrict__ C) {
    int gw = (blockIdx.x * blockDim.x + threadIdx.x) >> 5;
    int lane = threadIdx.x & 31;
    if (gw >= BATCH) return;
    int cnt = g_candCnt[gw];
    const float4* zr = (const float4*)(Z + (size_t)gw * DIM);
    float z2 = g_z2[gw];
    float bd = __int_as_float(0x7f800000);
    int bi = 0x7fffffff;
    if (cnt <= CAP) {
        for (int s = lane; s < cnt; s += 32) {
            int code = g_candIdx[gw * CAP + s];
            float dist = exact_dist(zr, code, C, z2);
            if (dist < bd || (dist == bd && code < bi)) { bd = dist; bi = code; }
        }
    } else {  // overflow fallback: exact full scan
        for (int code = lane; code < NCODES; code += 32) {
            float dist = exact_dist(zr, code, C, z2);
            if (dist < bd) { bd = dist; bi = code; }
        }
    }
#pragma unroll
    for (int off = 16; off; off >>= 1) {
        float od = __shfl_down_sync(0xffffffffu, bd, off);
        int oi = __shfl_down_sync(0xffffffffu, bi, off);
        if (od < bd || (od == bd && oi < bi)) { bd = od; bi = oi; }
    }
    if (lane == 0) g_idx[gw] = bi;
}

// ---------------- gather + straight-through + loss partials ----------------
__global__ void gather2_kernel(const float* __restrict__ Z, const float* __restrict__ C,
                               float* __restrict__ outZ, float* __restrict__ outIdx) {
    int gw = (blockIdx.x * blockDim.x + threadIdx.x) >> 5;
    int lane = threadIdx.x & 31;
    if (gw >= BATCH) return;
    int idx = g_idx[gw];
    const float4* zr = (const float4*)(Z + (size_t)gw * DIM);
    const float4* er = (const float4*)(C + (size_t)idx * DIM);
    float4* orow = (float4*)(outZ + (size_t)gw * DIM);
    double s = 0.0;
#pragma unroll
    for (int h = 0; h < 2; h++) {
        int i = h * 32 + lane;
        float4 z = zr[i], e = er[i];
        float dx = e.x - z.x, dy = e.y - z.y, dz = e.z - z.z, dw = e.w - z.w;
        float4 o;
        o.x = z.x + dx; o.y = z.y + dy; o.z = z.z + dz; o.w = z.w + dw;
        orow[i] = o;
        s += (double)(dx * dx) + (double)(dy * dy) + (double)(dz * dz) + (double)(dw * dw);
    }
#pragma unroll
    for (int off = 16; off; off >>= 1) s += __shfl_down_sync(0xffffffffu, s, off);
    if (lane == 0) { g_part[gw] = s; outIdx[gw] = (float)idx; }
}

__global__ void finalize_kernel(float* __restrict__ outS) {
    __shared__ double red[256];
    int t = threadIdx.x;
    double s = 0.0;
    for (int i = t; i < BATCH; i += 256) s += g_part[i];
    red[t] = s;
    __syncthreads();
#pragma unroll
    for (int off = 128; off; off >>= 1) {
        if (t < off) red[t] += red[t + off];
        __syncthreads();
    }
    if (t == 0) {
        float cb = (float)(red[0] / (double)((size_t)BATCH * DIM));
        float commit = cb;
        float vq = cb + 0.25f * commit;
        outS[0] = vq; outS[1] = cb; outS[2] = commit;
    }
}

// ---------------------------------------------------------------------------
extern "C" void kernel_launch(void* const* d_in, const int* in_sizes, int n_in,
                              void* d_out, int out_size) {
    (void)in_sizes; (void)n_in; (void)out_size;
    const float* Z = (const float*)d_in[0];
    const float* C = (const float*)d_in[1];
    float* out    = (float*)d_out;
    float* outZ   = out;
    float* outIdx = out + (size_t)BATCH * DIM;
    float* outS   = outIdx + BATCH;

    static bool attrSet = false;
    if (!attrSet) {
        cudaFuncSetAttribute(dist_mma_kernel,
                             cudaFuncAttributeMaxDynamicSharedMemorySize, SM_TOT);
        attrSet = true;
    }

    init_kernel<<<BATCH / 256, 256>>>();
    rowsq_z_kernel<<<(BATCH * 32) / 256, 256>>>(Z);
    rowsq_e_kernel<<<(NCODES * 32) / 256, 256>>>(C);
    dist_mma_kernel<<<BATCH / BM, 256, SM_TOT>>>(Z, C);
    refine_kernel<<<BATCH / 8, 256>>>(Z, C);
    gather2_kernel<<<BATCH / 8, 256>>>(Z, C, outZ, outIdx);
    finalize_kernel<<<1, 256>>>(outS);
}